// round 8
// baseline (speedup 1.0000x reference)
#include <cuda_runtime.h>
#include <cstdint>

#define N_NODES 50000
#define D 128
#define N_EDGES 500000
#define TILE_M 64
#define GBLK ((N_NODES + TILE_M - 1) / TILE_M)

// Scratch (no cudaMalloc).
__device__ float g_bufH1[N_NODES * D];
__device__ float g_bufH2[N_NODES * D];
__device__ float g_bufG1[N_NODES * D];

// ---- smem layout (bytes); A tile stride 132 floats ----
#define SM_ZN  0                     // 64*132*4   = 33792
#define SM_W   33792                 // 128*132*4  = 67584
#define SM_PAR 101376                // 512 floats = 2048
#define SM_RED 103424                // 256 floats = 1024
#define SM_TOT 104448                // <= 113664 -> 2 CTAs/SM

__device__ __forceinline__ float to_tf32(float x) {
    uint32_t u;
    asm("cvt.rna.tf32.f32 %0, %1;" : "=r"(u) : "f"(x));
    return __uint_as_float(u);
}

__device__ __forceinline__ void mma_tf32(float& d0, float& d1, float& d2, float& d3,
                                         float a0, float a1, float a2, float a3,
                                         float b0, float b1) {
    asm volatile(
        "mma.sync.aligned.m16n8k8.row.col.f32.tf32.tf32.f32 "
        "{%0,%1,%2,%3}, {%4,%5,%6,%7}, {%8,%9}, {%0,%1,%2,%3};"
        : "+f"(d0), "+f"(d1), "+f"(d2), "+f"(d3)
        : "r"(__float_as_uint(a0)), "r"(__float_as_uint(a1)),
          "r"(__float_as_uint(a2)), "r"(__float_as_uint(a3)),
          "r"(__float_as_uint(b0)), "r"(__float_as_uint(b1)));
}

__device__ __forceinline__ float warp_sum(float v) {
#pragma unroll
    for (int o = 16; o > 0; o >>= 1) v += __shfl_xor_sync(0xffffffffu, v, o);
    return v;
}

// Mainloop: warp tile 16 rows x 64 cols; acc[nt][4]. A,B stride 132.
__device__ __forceinline__ void mma_pass(const float* __restrict__ As,
                                         const float* __restrict__ Bs,
                                         float acc[8][4],
                                         int wr, int wc, int q, int tig) {
#pragma unroll
    for (int nt = 0; nt < 8; nt++)
#pragma unroll
        for (int j = 0; j < 4; j++) acc[nt][j] = 0.f;
#pragma unroll 4
    for (int kk = 0; kk < 16; kk++) {
        int c = kk * 8 + tig;
        int ra = wr * 16 + q;
        float a0 = As[ra * 132 + c];
        float a1 = As[(ra + 8) * 132 + c];
        float a2 = As[ra * 132 + c + 4];
        float a3 = As[(ra + 8) * 132 + c + 4];
#pragma unroll
        for (int nt = 0; nt < 8; nt++) {
            int n = wc * 64 + nt * 8 + q;
            mma_tf32(acc[nt][0], acc[nt][1], acc[nt][2], acc[nt][3],
                     a0, a1, a2, a3, Bs[n * 132 + c], Bs[n * 132 + c + 4]);
        }
    }
}

// relu+bias+LN epilogue -> gmem (fp32, or tf32-rounded if ROUND_TF32).
// Contains one internal __syncthreads.
template <bool ROUND_TF32>
__device__ __forceinline__ void epilogue_ln(
    float acc[8][4], const float* __restrict__ s_bias,
    const float* __restrict__ s_nw, const float* __restrict__ s_nb,
    float* __restrict__ red_sum, float* __restrict__ red_sq,
    float* __restrict__ gout,
    int row0, int nrows, int wr, int wc, int q, int tig) {
    float sums[2] = {0.f, 0.f}, sqs[2] = {0.f, 0.f};
#pragma unroll
    for (int nt = 0; nt < 8; nt++) {
        int c = wc * 64 + nt * 8 + 2 * tig;
        float x0 = fmaxf(acc[nt][0] + s_bias[c], 0.f);
        float x1 = fmaxf(acc[nt][1] + s_bias[c + 1], 0.f);
        float y0 = fmaxf(acc[nt][2] + s_bias[c], 0.f);
        float y1 = fmaxf(acc[nt][3] + s_bias[c + 1], 0.f);
        acc[nt][0] = x0; acc[nt][1] = x1; acc[nt][2] = y0; acc[nt][3] = y1;
        sums[0] += x0 + x1; sqs[0] += x0 * x0 + x1 * x1;
        sums[1] += y0 + y1; sqs[1] += y0 * y0 + y1 * y1;
    }
#pragma unroll
    for (int o = 1; o <= 2; o <<= 1) {
#pragma unroll
        for (int h = 0; h < 2; h++) {
            sums[h] += __shfl_xor_sync(0xffffffffu, sums[h], o);
            sqs[h]  += __shfl_xor_sync(0xffffffffu, sqs[h], o);
        }
    }
    if (tig == 0) {
#pragma unroll
        for (int h = 0; h < 2; h++) {
            int r = wr * 16 + q + h * 8;
            red_sum[wc * 64 + r] = sums[h];
            red_sq[wc * 64 + r]  = sqs[h];
        }
    }
    __syncthreads();
    float mu[2], rs[2];
#pragma unroll
    for (int h = 0; h < 2; h++) {
        int r = wr * 16 + q + h * 8;
        float ts = red_sum[r] + red_sum[64 + r];
        float tq = red_sq[r] + red_sq[64 + r];
        float m = ts * (1.0f / 128.0f);
        mu[h] = m;
        rs[h] = rsqrtf(tq * (1.0f / 128.0f) - m * m + 1e-5f);
    }
#pragma unroll
    for (int nt = 0; nt < 8; nt++) {
        int c = wc * 64 + nt * 8 + 2 * tig;
        float nw0 = s_nw[c], nw1 = s_nw[c + 1];
        float nb0 = s_nb[c], nb1 = s_nb[c + 1];
#pragma unroll
        for (int h = 0; h < 2; h++) {
            int gr = row0 + wr * 16 + q + h * 8;
            if (gr < nrows) {
                float v0 = (acc[nt][2 * h]     - mu[h]) * rs[h] * nw0 + nb0;
                float v1 = (acc[nt][2 * h + 1] - mu[h]) * rs[h] * nw1 + nb1;
                if (ROUND_TF32) { v0 = to_tf32(v0); v1 = to_tf32(v1); }
                *reinterpret_cast<float2*>(gout + (size_t)gr * D + c) =
                    make_float2(v0, v1);
            }
        }
    }
}

__global__ void __launch_bounds__(256, 2) fused_kernel(
    const float* __restrict__ z,
    const float* __restrict__ w1, const float* __restrict__ b1,
    const float* __restrict__ w2, const float* __restrict__ b2,
    const float* __restrict__ bw,
    const float* __restrict__ nw, const float* __restrict__ nb,
    float* __restrict__ h1_out, float* __restrict__ h2_out,
    float* __restrict__ g1_out, int nrows) {
    extern __shared__ char smem[];
    float*  ZN  = reinterpret_cast<float*>(smem + SM_ZN);
    float*  Ws  = reinterpret_cast<float*>(smem + SM_W);
    float*  par = reinterpret_cast<float*>(smem + SM_PAR);
    float*  red_sum = reinterpret_cast<float*>(smem + SM_RED);
    float*  red_sq  = red_sum + 128;
    float4* ZN4 = reinterpret_cast<float4*>(ZN);
    float4* Ws4 = reinterpret_cast<float4*>(Ws);

    const int tid  = threadIdx.x;
    const int lane = tid & 31;
    const int w    = tid >> 5;
    const int q    = lane >> 2;
    const int tig  = lane & 3;
    const int wr   = w & 3;       // row group (16 rows)
    const int wc   = w >> 2;      // col group (64 cols)
    const int row0 = blockIdx.x * TILE_M;

    // ---- stage raw z tile (64 rows) + W1 + params ----
#pragma unroll
    for (int i = 0; i < 8; i++) {
        int idx = tid + i * 256;
        int r = idx >> 5, c4 = idx & 31;
        float4 v = make_float4(0.f, 0.f, 0.f, 0.f);
        int gr = row0 + r;
        if (gr < nrows) v = reinterpret_cast<const float4*>(z)[(size_t)gr * 32 + c4];
        ZN4[r * 33 + c4] = v;
    }
#pragma unroll
    for (int i = 0; i < 16; i++) {
        int idx = tid + i * 256;
        int r = idx >> 5, c4 = idx & 31;
        float4 v = reinterpret_cast<const float4*>(w1)[idx];
        v.x = to_tf32(v.x); v.y = to_tf32(v.y); v.z = to_tf32(v.z); v.w = to_tf32(v.w);
        Ws4[r * 33 + c4] = v;
    }
    for (int idx = tid; idx < 512; idx += 256)
        par[idx] = (idx < 128)   ? b1[idx]
                 : (idx < 256)   ? b2[idx - 128]
                 : (idx < 384)   ? nw[idx - 256]
                                 : nb[idx - 384];
    __syncthreads();

    float* s_b1 = par;
    float* s_b2 = par + 128;
    float* s_nw = par + 256;
    float* s_nb = par + 384;

    // ---- LN(z) in place, tf32 (warp w: rows w*8 .. w*8+8) ----
    {
        float4 w4  = reinterpret_cast<float4*>(s_nw)[lane];
        float4 nb4 = reinterpret_cast<float4*>(s_nb)[lane];
#pragma unroll
        for (int i = 0; i < 8; i++) {
            int r = w * 8 + i;
            float4 v = ZN4[r * 33 + lane];
            float s  = warp_sum(v.x + v.y + v.z + v.w);
            float sq = warp_sum(v.x * v.x + v.y * v.y + v.z * v.z + v.w * v.w);
            float mu = s * (1.0f / 128.0f);
            float rs = rsqrtf(sq * (1.0f / 128.0f) - mu * mu + 1e-5f);
            v.x = to_tf32((v.x - mu) * rs * w4.x + nb4.x);
            v.y = to_tf32((v.y - mu) * rs * w4.y + nb4.y);
            v.z = to_tf32((v.z - mu) * rs * w4.z + nb4.z);
            v.w = to_tf32((v.w - mu) * rs * w4.w + nb4.w);
            ZN4[r * 33 + lane] = v;
        }
    }
    __syncthreads();

    float acc[8][4];

    // ===== PASS 1: H1 = LN(relu(ZN @ W1^T + b1)) -> gmem (tf32 values) =====
    mma_pass(ZN, Ws, acc, wr, wc, q, tig);
    __syncthreads();  // W reads done -> restage safe
#pragma unroll
    for (int i = 0; i < 16; i++) {   // restage W <- W2
        int idx = tid + i * 256;
        int r = idx >> 5, c4 = idx & 31;
        float4 v = reinterpret_cast<const float4*>(w2)[idx];
        v.x = to_tf32(v.x); v.y = to_tf32(v.y); v.z = to_tf32(v.z); v.w = to_tf32(v.w);
        Ws4[r * 33 + c4] = v;
    }
    epilogue_ln<true>(acc, s_b1, s_nw, s_nb, red_sum, red_sq, h1_out,
                      row0, nrows, wr, wc, q, tig);
    __syncthreads();  // W2 staged; red arrays free

    // ===== PASS 2: H2 = LN(relu(ZN @ W2^T + b2)) -> gmem =====
    mma_pass(ZN, Ws, acc, wr, wc, q, tig);
    __syncthreads();  // ZN + W reads done -> restage both
    // restage W <- bil_w^T: Ws[f][d] = bw[d][f]
#pragma unroll
    for (int i = 0; i < 64; i++) {
        int idx = tid + i * 256;
        int d = idx >> 7, f = idx & 127;
        Ws[f * 132 + d] = to_tf32(bw[idx]);
    }
    // restage ZN <- H1 (values already tf32; written by this CTA -> L2 hit)
#pragma unroll
    for (int i = 0; i < 8; i++) {
        int idx = tid + i * 256;
        int r = idx >> 5, c4 = idx & 31;
        float4 v = make_float4(0.f, 0.f, 0.f, 0.f);
        int gr = row0 + r;
        if (gr < nrows)
            v = reinterpret_cast<const float4*>(h1_out)[(size_t)gr * 32 + c4];
        ZN4[r * 33 + c4] = v;
    }
    epilogue_ln<false>(acc, s_b2, s_nw, s_nb, red_sum, red_sq, h2_out,
                       row0, nrows, wr, wc, q, tig);
    __syncthreads();  // H1 tile + bw staged

    // ===== PASS 3: G1 = H1 @ bil_w -> gmem =====
    mma_pass(ZN, Ws, acc, wr, wc, q, tig);
#pragma unroll
    for (int nt = 0; nt < 8; nt++) {
        int c = wc * 64 + nt * 8 + 2 * tig;
#pragma unroll
        for (int h = 0; h < 2; h++) {
            int gr = row0 + wr * 16 + q + h * 8;
            if (gr < nrows)
                *reinterpret_cast<float2*>(g1_out + (size_t)gr * D + c) =
                    make_float2(acc[nt][2 * h], acc[nt][2 * h + 1]);
        }
    }
}

// ---------------------------------------------------------------------------
// Edge kernel v4: 8 edges/warp = 2 batches x 4 edges; 8 lanes per edge.
//   lane = j*8 + s; per k, the 8 lanes of an edge read one full 128B line
//   (perfect wavefronts) and each lane carries 16 independent L2-only loads.
// ---------------------------------------------------------------------------
__global__ void __launch_bounds__(256) edge_kernel(
    const int* __restrict__ arcs,
    const float* __restrict__ G1,
    const float* __restrict__ H2,
    const float* __restrict__ bilb,
    float* __restrict__ out) {
    const int warp = (blockIdx.x * blockDim.x + threadIdx.x) >> 5;
    const int lane = threadIdx.x & 31;
    const int j    = lane >> 3;   // edge-in-batch (0..3)
    const int s    = lane & 7;    // sub-lane within edge
    const int e0   = warp * 8 + j;
    if (e0 >= N_EDGES) return;

    int2 a[2];
    a[0] = __ldg(reinterpret_cast<const int2*>(arcs) + e0);
    a[1] = __ldg(reinterpret_cast<const int2*>(arcs) + e0 + 4);

    float4 g[2][4], h[2][4];
#pragma unroll
    for (int b = 0; b < 2; b++) {
        const float4* g4 = reinterpret_cast<const float4*>(G1 + (size_t)a[b].x * D);
        const float4* h4 = reinterpret_cast<const float4*>(H2 + (size_t)a[b].y * D);
#pragma unroll
        for (int k = 0; k < 4; k++) {
            g[b][k] = __ldcg(g4 + s + 8 * k);
            h[b][k] = __ldcg(h4 + s + 8 * k);
        }
    }
#pragma unroll
    for (int b = 0; b < 2; b++) {
        float v = 0.f;
#pragma unroll
        for (int k = 0; k < 4; k++) {
            v += g[b][k].x * h[b][k].x;
            v += g[b][k].y * h[b][k].y;
            v += g[b][k].z * h[b][k].z;
            v += g[b][k].w * h[b][k].w;
        }
        v += __shfl_xor_sync(0xffffffffu, v, 1);
        v += __shfl_xor_sync(0xffffffffu, v, 2);
        v += __shfl_xor_sync(0xffffffffu, v, 4);
        if (s == 0) out[e0 + b * 4] = v + bilb[0];
    }
}

// ---------------------------------------------------------------------------
extern "C" void kernel_launch(void* const* d_in, const int* in_sizes, int n_in,
                              void* d_out, int out_size) {
    const float* z    = (const float*)d_in[0];
    const int*   arcs = (const int*)d_in[1];
    const float* w1   = (const float*)d_in[2];
    const float* b1   = (const float*)d_in[3];
    const float* w2   = (const float*)d_in[4];
    const float* b2   = (const float*)d_in[5];
    const float* bw   = (const float*)d_in[6];
    const float* bb   = (const float*)d_in[7];
    const float* nw   = (const float*)d_in[8];
    const float* nb   = (const float*)d_in[9];
    float*       out  = (float*)d_out;

    float *h1buf, *h2buf, *g1buf;
    cudaGetSymbolAddress((void**)&h1buf, g_bufH1);
    cudaGetSymbolAddress((void**)&h2buf, g_bufH2);
    cudaGetSymbolAddress((void**)&g1buf, g_bufG1);

    cudaFuncSetAttribute(fused_kernel,
                         cudaFuncAttributeMaxDynamicSharedMemorySize, SM_TOT);

    fused_kernel<<<GBLK, 256, SM_TOT>>>(z, w1, b1, w2, b2, bw, nw, nb,
                                        h1buf, h2buf, g1buf, N_NODES);
    // 8 edges per warp, 8 warps per block -> 64 edges per block
    edge_kernel<<<(N_EDGES + 63) / 64, 256>>>(arcs, g1buf, h2buf, bb, out);
}

// round 9
// speedup vs baseline: 1.1328x; 1.1328x over previous
#include <cuda_runtime.h>
#include <cstdint>

#define N_NODES 50000
#define D 128
#define N_EDGES 500000
#define TILE_M 128
#define GBLK ((N_NODES + TILE_M - 1) / TILE_M)
#define NTHREADS 512

// Scratch (no cudaMalloc). H1/ZN never leave the CTA.
__device__ float g_bufH2[N_NODES * D];
__device__ float g_bufG1[N_NODES * D];

// ---- smem layout (bytes); tiles at float row-stride 132 ----
#define SM_ZN  0        // 128*132*4 = 67584
#define SM_W   67584    // 67584
#define SM_H1  135168   // 67584
#define SM_PAR 202752   // 512 floats
#define SM_RED 204800   // 512 floats (sum 256 + sq 256)
#define SM_TOT 206848

__device__ __forceinline__ float to_tf32(float x) {
    uint32_t u;
    asm("cvt.rna.tf32.f32 %0, %1;" : "=r"(u) : "f"(x));
    return __uint_as_float(u);
}

__device__ __forceinline__ void mma_tf32(float& d0, float& d1, float& d2, float& d3,
                                         float a0, float a1, float a2, float a3,
                                         float b0, float b1) {
    asm volatile(
        "mma.sync.aligned.m16n8k8.row.col.f32.tf32.tf32.f32 "
        "{%0,%1,%2,%3}, {%4,%5,%6,%7}, {%8,%9}, {%0,%1,%2,%3};"
        : "+f"(d0), "+f"(d1), "+f"(d2), "+f"(d3)
        : "r"(__float_as_uint(a0)), "r"(__float_as_uint(a1)),
          "r"(__float_as_uint(a2)), "r"(__float_as_uint(a3)),
          "r"(__float_as_uint(b0)), "r"(__float_as_uint(b1)));
}

__device__ __forceinline__ float warp_sum(float v) {
#pragma unroll
    for (int o = 16; o > 0; o >>= 1) v += __shfl_xor_sync(0xffffffffu, v, o);
    return v;
}

// Mainloop: warp tile 16 rows x 64 cols; acc[nt][4]. A,B at stride 132.
__device__ __forceinline__ void mma_pass(const float* __restrict__ As,
                                         const float* __restrict__ Bs,
                                         float acc[8][4],
                                         int wr, int wc, int q, int tig) {
#pragma unroll
    for (int nt = 0; nt < 8; nt++)
#pragma unroll
        for (int j = 0; j < 4; j++) acc[nt][j] = 0.f;
    const int ra = wr * 16 + q;
#pragma unroll 4
    for (int kk = 0; kk < 16; kk++) {
        int c = kk * 8 + tig;
        float a0 = As[ra * 132 + c];
        float a1 = As[(ra + 8) * 132 + c];
        float a2 = As[ra * 132 + c + 4];
        float a3 = As[(ra + 8) * 132 + c + 4];
#pragma unroll
        for (int nt = 0; nt < 8; nt++) {
            int n = wc * 64 + nt * 8 + q;
            mma_tf32(acc[nt][0], acc[nt][1], acc[nt][2], acc[nt][3],
                     a0, a1, a2, a3, Bs[n * 132 + c], Bs[n * 132 + c + 4]);
        }
    }
}

// relu+bias+LN epilogue. TO_SMEM: tf32 -> H1 smem; else fp32 -> gmem.
// Contains one internal __syncthreads — call from all threads.
template <bool TO_SMEM>
__device__ __forceinline__ void epilogue_ln(
    float acc[8][4], const float* __restrict__ s_bias,
    const float* __restrict__ s_nw, const float* __restrict__ s_nb,
    float* __restrict__ red_sum, float* __restrict__ red_sq,
    float* __restrict__ H1, float* __restrict__ gout,
    int row0, int nrows, int wr, int wc, int q, int tig) {
    float sums[2] = {0.f, 0.f}, sqs[2] = {0.f, 0.f};
#pragma unroll
    for (int nt = 0; nt < 8; nt++) {
        int c = wc * 64 + nt * 8 + 2 * tig;
        float x0 = fmaxf(acc[nt][0] + s_bias[c], 0.f);
        float x1 = fmaxf(acc[nt][1] + s_bias[c + 1], 0.f);
        float y0 = fmaxf(acc[nt][2] + s_bias[c], 0.f);
        float y1 = fmaxf(acc[nt][3] + s_bias[c + 1], 0.f);
        acc[nt][0] = x0; acc[nt][1] = x1; acc[nt][2] = y0; acc[nt][3] = y1;
        sums[0] += x0 + x1; sqs[0] += x0 * x0 + x1 * x1;
        sums[1] += y0 + y1; sqs[1] += y0 * y0 + y1 * y1;
    }
#pragma unroll
    for (int o = 1; o <= 2; o <<= 1) {
#pragma unroll
        for (int h = 0; h < 2; h++) {
            sums[h] += __shfl_xor_sync(0xffffffffu, sums[h], o);
            sqs[h]  += __shfl_xor_sync(0xffffffffu, sqs[h], o);
        }
    }
    if (tig == 0) {
#pragma unroll
        for (int h = 0; h < 2; h++) {
            int r = wr * 16 + q + h * 8;
            red_sum[wc * 128 + r] = sums[h];
            red_sq[wc * 128 + r]  = sqs[h];
        }
    }
    __syncthreads();
    float mu[2], rs[2];
#pragma unroll
    for (int h = 0; h < 2; h++) {
        int r = wr * 16 + q + h * 8;
        float ts = red_sum[r] + red_sum[128 + r];
        float tq = red_sq[r] + red_sq[128 + r];
        float m = ts * (1.0f / 128.0f);
        mu[h] = m;
        rs[h] = rsqrtf(tq * (1.0f / 128.0f) - m * m + 1e-5f);
    }
#pragma unroll
    for (int nt = 0; nt < 8; nt++) {
        int c = wc * 64 + nt * 8 + 2 * tig;
        float nw0 = s_nw[c], nw1 = s_nw[c + 1];
        float nb0 = s_nb[c], nb1 = s_nb[c + 1];
#pragma unroll
        for (int h = 0; h < 2; h++) {
            int r = wr * 16 + q + h * 8;
            float v0 = (acc[nt][2 * h]     - mu[h]) * rs[h] * nw0 + nb0;
            float v1 = (acc[nt][2 * h + 1] - mu[h]) * rs[h] * nw1 + nb1;
            if (TO_SMEM) {
                *reinterpret_cast<float2*>(&H1[r * 132 + c]) =
                    make_float2(to_tf32(v0), to_tf32(v1));
            } else {
                int gr = row0 + r;
                if (gr < nrows)
                    *reinterpret_cast<float2*>(gout + (size_t)gr * D + c) =
                        make_float2(v0, v1);
            }
        }
    }
}

__global__ void __launch_bounds__(NTHREADS, 1) fused_kernel(
    const float* __restrict__ z,
    const float* __restrict__ w1, const float* __restrict__ b1,
    const float* __restrict__ w2, const float* __restrict__ b2,
    const float* __restrict__ bw,
    const float* __restrict__ nw, const float* __restrict__ nb,
    float* __restrict__ h2_out, float* __restrict__ g1_out, int nrows) {
    extern __shared__ char smem[];
    float*  ZN  = reinterpret_cast<float*>(smem + SM_ZN);
    float*  Ws  = reinterpret_cast<float*>(smem + SM_W);
    float*  H1  = reinterpret_cast<float*>(smem + SM_H1);
    float*  par = reinterpret_cast<float*>(smem + SM_PAR);
    float*  red_sum = reinterpret_cast<float*>(smem + SM_RED);
    float*  red_sq  = red_sum + 256;
    float4* ZN4 = reinterpret_cast<float4*>(ZN);
    float4* Ws4 = reinterpret_cast<float4*>(Ws);

    const int tid  = threadIdx.x;
    const int lane = tid & 31;
    const int w    = tid >> 5;    // 0..15
    const int q    = lane >> 2;
    const int tig  = lane & 3;
    const int wr   = w & 7;       // row group (16 rows)
    const int wc   = w >> 3;      // col group (64 cols)
    const int row0 = blockIdx.x * TILE_M;

    // ---- stage raw z tile + W1 + params ----
#pragma unroll
    for (int i = 0; i < 8; i++) {
        int idx = tid + i * NTHREADS;
        int r = idx >> 5, c4 = idx & 31;
        float4 v = make_float4(0.f, 0.f, 0.f, 0.f);
        int gr = row0 + r;
        if (gr < nrows) v = reinterpret_cast<const float4*>(z)[(size_t)gr * 32 + c4];
        ZN4[r * 33 + c4] = v;
    }
#pragma unroll
    for (int i = 0; i < 8; i++) {
        int idx = tid + i * NTHREADS;
        int r = idx >> 5, c4 = idx & 31;
        float4 v = reinterpret_cast<const float4*>(w1)[idx];
        v.x = to_tf32(v.x); v.y = to_tf32(v.y); v.z = to_tf32(v.z); v.w = to_tf32(v.w);
        Ws4[r * 33 + c4] = v;
    }
    if (tid < 512)
        par[tid] = (tid < 128)   ? b1[tid]
                 : (tid < 256)   ? b2[tid - 128]
                 : (tid < 384)   ? nw[tid - 256]
                                 : nb[tid - 384];
    __syncthreads();

    float* s_b1 = par;
    float* s_b2 = par + 128;
    float* s_nw = par + 256;
    float* s_nb = par + 384;

    // ---- LN(z) in place, tf32 (warp w: rows w*8 .. w*8+7) ----
    {
        float4 w4  = reinterpret_cast<float4*>(s_nw)[lane];
        float4 nb4 = reinterpret_cast<float4*>(s_nb)[lane];
#pragma unroll
        for (int i = 0; i < 8; i++) {
            int r = w * 8 + i;
            float4 v = ZN4[r * 33 + lane];
            float s  = warp_sum(v.x + v.y + v.z + v.w);
            float sq = warp_sum(v.x * v.x + v.y * v.y + v.z * v.z + v.w * v.w);
            float mu = s * (1.0f / 128.0f);
            float rs = rsqrtf(sq * (1.0f / 128.0f) - mu * mu + 1e-5f);
            v.x = to_tf32((v.x - mu) * rs * w4.x + nb4.x);
            v.y = to_tf32((v.y - mu) * rs * w4.y + nb4.y);
            v.z = to_tf32((v.z - mu) * rs * w4.z + nb4.z);
            v.w = to_tf32((v.w - mu) * rs * w4.w + nb4.w);
            ZN4[r * 33 + lane] = v;
        }
    }
    __syncthreads();

    float acc[8][4];

    // ===== PASS 1: H1 = LN(relu(ZN @ W1^T + b1)) -> smem (tf32) =====
    mma_pass(ZN, Ws, acc, wr, wc, q, tig);
    __syncthreads();  // W reads done -> restage safe
#pragma unroll
    for (int i = 0; i < 8; i++) {   // restage W <- W2
        int idx = tid + i * NTHREADS;
        int r = idx >> 5, c4 = idx & 31;
        float4 v = reinterpret_cast<const float4*>(w2)[idx];
        v.x = to_tf32(v.x); v.y = to_tf32(v.y); v.z = to_tf32(v.z); v.w = to_tf32(v.w);
        Ws4[r * 33 + c4] = v;
    }
    epilogue_ln<true>(acc, s_b1, s_nw, s_nb, red_sum, red_sq, H1, nullptr,
                      row0, nrows, wr, wc, q, tig);
    __syncthreads();  // H1 writes + W2 staging visible

    // ===== PASS 2: H2 = LN(relu(ZN @ W2^T + b2)) -> gmem =====
    mma_pass(ZN, Ws, acc, wr, wc, q, tig);
    __syncthreads();  // W reads done -> restage safe
#pragma unroll
    for (int i = 0; i < 32; i++) {  // restage W <- bil_w^T: Ws[f][d]=bw[d][f]
        int idx = tid + i * NTHREADS;
        int d = idx >> 7, f = idx & 127;
        Ws[f * 132 + d] = to_tf32(bw[idx]);
    }
    epilogue_ln<false>(acc, s_b2, s_nw, s_nb, red_sum, red_sq, nullptr, h2_out,
                       row0, nrows, wr, wc, q, tig);
    __syncthreads();  // bw staging visible; H1 stable

    // ===== PASS 3: G1 = H1 @ bil_w -> gmem =====
    mma_pass(H1, Ws, acc, wr, wc, q, tig);
#pragma unroll
    for (int nt = 0; nt < 8; nt++) {
        int c = wc * 64 + nt * 8 + 2 * tig;
#pragma unroll
        for (int h = 0; h < 2; h++) {
            int gr = row0 + wr * 16 + q + h * 8;
            if (gr < nrows)
                *reinterpret_cast<float2*>(g1_out + (size_t)gr * D + c) =
                    make_float2(acc[nt][2 * h], acc[nt][2 * h + 1]);
        }
    }
}

// ---------------------------------------------------------------------------
// Edge kernel v4 (unchanged from R8): 8 edges/warp = 2 batches x 4 edges;
// 8 lanes per edge -> full 128B wavefronts, 16 independent L2-only loads/lane.
// ---------------------------------------------------------------------------
__global__ void __launch_bounds__(256) edge_kernel(
    const int* __restrict__ arcs,
    const float* __restrict__ G1,
    const float* __restrict__ H2,
    const float* __restrict__ bilb,
    float* __restrict__ out) {
    const int warp = (blockIdx.x * blockDim.x + threadIdx.x) >> 5;
    const int lane = threadIdx.x & 31;
    const int j    = lane >> 3;   // edge-in-batch (0..3)
    const int s    = lane & 7;    // sub-lane within edge
    const int e0   = warp * 8 + j;
    if (e0 >= N_EDGES) return;

    int2 a[2];
    a[0] = __ldg(reinterpret_cast<const int2*>(arcs) + e0);
    a[1] = __ldg(reinterpret_cast<const int2*>(arcs) + e0 + 4);

    float4 g[2][4], h[2][4];
#pragma unroll
    for (int b = 0; b < 2; b++) {
        const float4* g4 = reinterpret_cast<const float4*>(G1 + (size_t)a[b].x * D);
        const float4* h4 = reinterpret_cast<const float4*>(H2 + (size_t)a[b].y * D);
#pragma unroll
        for (int k = 0; k < 4; k++) {
            g[b][k] = __ldcg(g4 + s + 8 * k);
            h[b][k] = __ldcg(h4 + s + 8 * k);
        }
    }
#pragma unroll
    for (int b = 0; b < 2; b++) {
        float v = 0.f;
#pragma unroll
        for (int k = 0; k < 4; k++) {
            v += g[b][k].x * h[b][k].x;
            v += g[b][k].y * h[b][k].y;
            v += g[b][k].z * h[b][k].z;
            v += g[b][k].w * h[b][k].w;
        }
        v += __shfl_xor_sync(0xffffffffu, v, 1);
        v += __shfl_xor_sync(0xffffffffu, v, 2);
        v += __shfl_xor_sync(0xffffffffu, v, 4);
        if (s == 0) out[e0 + b * 4] = v + bilb[0];
    }
}

// ---------------------------------------------------------------------------
extern "C" void kernel_launch(void* const* d_in, const int* in_sizes, int n_in,
                              void* d_out, int out_size) {
    const float* z    = (const float*)d_in[0];
    const int*   arcs = (const int*)d_in[1];
    const float* w1   = (const float*)d_in[2];
    const float* b1   = (const float*)d_in[3];
    const float* w2   = (const float*)d_in[4];
    const float* b2   = (const float*)d_in[5];
    const float* bw   = (const float*)d_in[6];
    const float* bb   = (const float*)d_in[7];
    const float* nw   = (const float*)d_in[8];
    const float* nb   = (const float*)d_in[9];
    float*       out  = (float*)d_out;

    float *h2buf, *g1buf;
    cudaGetSymbolAddress((void**)&h2buf, g_bufH2);
    cudaGetSymbolAddress((void**)&g1buf, g_bufG1);

    cudaFuncSetAttribute(fused_kernel,
                         cudaFuncAttributeMaxDynamicSharedMemorySize, SM_TOT);

    fused_kernel<<<GBLK, NTHREADS, SM_TOT>>>(z, w1, b1, w2, b2, bw, nw, nb,
                                             h2buf, g1buf, N_NODES);
    // 8 edges per warp, 8 warps per block -> 64 edges per block
    edge_kernel<<<(N_EDGES + 63) / 64, 256>>>(arcs, g1buf, h2buf, bb, out);
}